// round 17
// baseline (speedup 1.0000x reference)
#include <cuda_runtime.h>
#include <cuda_fp16.h>
#include <cstdint>
#include <math.h>

// Problem constants
#define BB   8
#define LL   128
#define SS   100
#define TT   100
#define QD   512
#define FD   2048
#define HD   512
#define OD   512

#define KP   224          // padded K for ctx gemm (200 -> 224)

// Scratch (device globals; no allocation APIs allowed)
__device__ __half g_in_q[BB * LL * QD];
__device__ __half g_in_s[BB * SS * FD];
__device__ __half g_in_t[BB * TT * FD];
__device__ __half g_q[BB * LL * HD];
__device__ __half g_key[BB * (SS + TT) * HD];
__device__ __half g_keyT[BB * HD * KP];       // [b][c][j], pads stay 0 (module-zeroed)
__device__ __half g_ctx[BB * LL * HD];
__device__ float  g_sc[BB * LL * 256];        // scores fp32, 256-stride
__device__ __half g_wqT[HD * QD];
__device__ __half g_wsT[HD * FD];
__device__ __half g_woT[OD * (QD + HD)];

// ---------------------------------------------------------------------------
__device__ __forceinline__ uint32_t s2u(const void* p) {
    uint32_t a;
    asm("{ .reg .u64 t; cvta.to.shared.u64 t, %1; cvt.u32.u64 %0, t; }" : "=r"(a) : "l"(p));
    return a;
}
__device__ __forceinline__ void cp16(uint32_t dst, const void* src) {
    asm volatile("cp.async.cg.shared.global [%0], [%1], 16;" :: "r"(dst), "l"(src));
}
#define CP_COMMIT()  asm volatile("cp.async.commit_group;" ::: "memory")
#define CP_WAITG(n)  asm volatile("cp.async.wait_group %0;" :: "n"(n) : "memory")

#define LDSM4(r, a) \
    asm volatile("ldmatrix.sync.aligned.m8n8.x4.shared.b16 {%0,%1,%2,%3}, [%4];" \
        : "=r"((r)[0]), "=r"((r)[1]), "=r"((r)[2]), "=r"((r)[3]) : "r"(a))

#define MMA_F16(d, a, b0, b1) \
    asm volatile("mma.sync.aligned.m16n8k16.row.col.f32.f16.f16.f32 " \
        "{%0,%1,%2,%3}, {%4,%5,%6,%7}, {%8,%9}, {%0,%1,%2,%3};" \
        : "+f"((d)[0]), "+f"((d)[1]), "+f"((d)[2]), "+f"((d)[3]) \
        : "r"((a)[0]), "r"((a)[1]), "r"((a)[2]), "r"((a)[3]), "r"(b0), "r"(b1))

extern __shared__ __align__(128) float dynsm[];

// ---------------------------------------------------------------------------
// prepAll: weight transposes -> fp16 | input f32->f16 conversion
// ---------------------------------------------------------------------------
__global__ __launch_bounds__(256) void prepAll(
    const float* __restrict__ Wq, __half* __restrict__ wqT,
    const float* __restrict__ Ws, __half* __restrict__ wsT,
    const float* __restrict__ Wo, __half* __restrict__ woT,
    const float* __restrict__ query, const float* __restrict__ src,
    const float* __restrict__ trg,
    __half* __restrict__ q16, __half* __restrict__ s16, __half* __restrict__ t16)
{
    int bid = blockIdx.x;
    if (bid < 1792) {
        __shared__ float t[32][33];
        const float* W; __half* WT; int K;
        if (bid < 256)       { W = Wq; WT = wqT; K = 512;  }
        else if (bid < 1280) { W = Ws; WT = wsT; K = 2048; bid -= 256;  }
        else                 { W = Wo; WT = woT; K = 1024; bid -= 1280; }
        int k0 = (bid >> 4) * 32, n0 = (bid & 15) * 32;
        int x = threadIdx.x & 31, y = threadIdx.x >> 5;
#pragma unroll
        for (int i = 0; i < 32; i += 8)
            t[y + i][x] = W[(long)(k0 + y + i) * 512 + n0 + x];
        __syncthreads();
#pragma unroll
        for (int i = 0; i < 32; i += 8)
            WT[(long)(n0 + y + i) * K + k0 + x] = __float2half_rn(t[x][y + i]);
        return;
    }
    int i = (bid - 1792) * 256 + threadIdx.x;     // pair-of-float4 index
    if (i < 475136) {
        const float4* s; __half* d;
        if (i < 65536)       { s = (const float4*)query + i * 2;            d = q16 + i * 8; }
        else if (i < 270336) { int j = i - 65536;  s = (const float4*)src + j * 2; d = s16 + j * 8; }
        else                 { int j = i - 270336; s = (const float4*)trg + j * 2; d = t16 + j * 8; }
        float4 v0 = s[0], v1 = s[1];
        __half2 h[4];
        h[0] = __floats2half2_rn(v0.x, v0.y);
        h[1] = __floats2half2_rn(v0.z, v0.w);
        h[2] = __floats2half2_rn(v1.x, v1.y);
        h[3] = __floats2half2_rn(v1.z, v1.w);
        *(uint4*)d = *(uint4*)h;
    }
}

// ---------------------------------------------------------------------------
// Generalized batched fp16 mma.sync GEMM (3 descriptors per launch) with
// optional independent transpose CTAs appended after nGemm.
// ---------------------------------------------------------------------------
struct GD {
    const __half* A0; const __half* A1; int aSplit; int lda; int bsA;
    const __half* B0; const __half* B1; int bSplit; int ldb; int bsB;
    void* C; int ldc; int bsC;
    const float* bias;
    int Ktot; int kSplit; int outHalf;
    int Mreal; int Nreal;
    int mt; int nt; int batches;
};
struct AUXT { const __half* key; __half* keyT; int nGemm; };

#define STG_BYTES 10240u
#define ABASE(s) ((s) * STG_BYTES)
#define BBASE(s) ((s) * STG_BYTES + 5120u)
#define DSMEM_G  30720

__global__ __launch_bounds__(128) void gemm_mma(GD ga, GD gb, GD gc,
                                                int nA, int nAB, AUXT aux)
{
    const int tid = threadIdx.x;

    // ----- independent transpose role (no dependency on gemm blocks) -----
    if (aux.key && blockIdx.x >= (unsigned)aux.nGemm) {
        __half (*tt)[65] = (__half(*)[65])dynsm;
        int abid = blockIdx.x - aux.nGemm;       // 0..255
        const int b  = abid >> 5;
        const int rm = abid & 31;
        const int c0 = (rm >> 2) * 64;
        const int j0 = (rm & 3) * 64;
        const int x = tid & 63, y = tid >> 6;    // 64 x 2
#pragma unroll
        for (int i = 0; i < 64; i += 2) {
            int j = j0 + y + i; if (j > 199) j = 199;
            int srow = (j < SS) ? b * SS + j : BB * SS + b * TT + (j - SS);
            tt[y + i][x] = aux.key[(long)srow * HD + c0 + x];
        }
        __syncthreads();
        if (j0 + x < 200) {
#pragma unroll
            for (int i = 0; i < 64; i += 2)
                aux.keyT[(long)(b * HD + c0 + y + i) * KP + j0 + x] = tt[x][y + i];
        }
        return;
    }

    GD g; int lbid;
    if (blockIdx.x < (unsigned)nA)        { g = ga; lbid = blockIdx.x; }
    else if (blockIdx.x < (unsigned)nAB)  { g = gb; lbid = blockIdx.x - nA; }
    else                                  { g = gc; lbid = blockIdx.x - nAB; }

    const int tilesTot = g.mt * g.nt * g.batches;
    const int within = lbid % tilesTot;
    const int kz     = lbid / tilesTot;
    const int batch  = within / (g.mt * g.nt);
    const int rem    = within % (g.mt * g.nt);
    const int bm = (rem / g.nt) * 64;
    const int bn = (rem % g.nt) * 64;

    const int Kslice = g.Ktot / g.kSplit;
    const int kOff   = kz * Kslice;
    const int T = Kslice >> 5;

    const int lane = tid & 31;
    const int wid  = tid >> 5;
    const int wm   = (wid & 1) * 32;
    const int wn   = (wid >> 1) * 32;

    const uint32_t smem = s2u(dynsm);

    const int lr     = lane & 7;
    const int rowoff = ((lane >> 3) & 1) * 8;
    const int coff   = lane >> 4;
    const int arow   = wm + rowoff + lr;
    const int brow   = wn + rowoff + lr;

    float acc[2][4][4];
#pragma unroll
    for (int mi = 0; mi < 2; mi++)
#pragma unroll
        for (int ni = 0; ni < 4; ni++)
#pragma unroll
            for (int j = 0; j < 4; j++) acc[mi][ni][j] = 0.f;

    auto issue_tile = [&](int t, int s) {
        const int k0 = kOff + (t << 5);
#pragma unroll
        for (int i = 0; i < 2; i++) {
            int idx = tid + (i << 7);
            int r = idx >> 2, c = idx & 3;
            uint32_t dst = smem + ABASE(s) + (uint32_t)(r * 80 + c * 16);
            int gr = bm + r; if (gr >= g.Mreal) gr = g.Mreal - 1;
            const __half* p = (gr < g.aSplit)
                ? g.A0 + (long)gr * g.lda
                : g.A1 + (long)(gr - g.aSplit) * g.lda;
            cp16(dst, p + (long)batch * g.bsA + k0 + c * 8);
        }
#pragma unroll
        for (int i = 0; i < 2; i++) {
            int idx = tid + (i << 7);
            int r = idx >> 2, c = idx & 3;
            uint32_t dst = smem + BBASE(s) + (uint32_t)(r * 80 + c * 16);
            int gc = bn + r; if (gc >= g.Nreal) gc = g.Nreal - 1;
            const __half* p = (gc < g.bSplit)
                ? g.B0 + (long)gc * g.ldb
                : g.B1 + (long)(gc - g.bSplit) * g.ldb;
            cp16(dst, p + (long)batch * g.bsB + k0 + c * 8);
        }
    };

    issue_tile(0, 0); CP_COMMIT();
    issue_tile(1, 1); CP_COMMIT();

    int s = 0;
    for (int t = 0; t < T; t++) {
        CP_WAITG(1);
        __syncthreads();
        int sn = s + 2; if (sn >= 3) sn -= 3;
        if (t + 2 < T) issue_tile(t + 2, sn);
        CP_COMMIT();

        const uint32_t ab = smem + ABASE(s);
        const uint32_t bb = smem + BBASE(s);
#pragma unroll
        for (int ks = 0; ks < 2; ks++) {
            uint32_t a[2][4], bf[2][4];
#pragma unroll
            for (int mi = 0; mi < 2; mi++) {
                uint32_t ad = ab + (uint32_t)((arow + mi * 16) * 80 + ((ks << 1) + coff) * 16);
                LDSM4(a[mi], ad);
            }
#pragma unroll
            for (int ng = 0; ng < 2; ng++) {
                uint32_t bd = bb + (uint32_t)((brow + ng * 16) * 80 + ((ks << 1) + coff) * 16);
                LDSM4(bf[ng], bd);
            }
#pragma unroll
            for (int mi = 0; mi < 2; mi++)
#pragma unroll
                for (int ni = 0; ni < 4; ni++) {
                    int ng = ni >> 1, sel = ni & 1;
                    MMA_F16(acc[mi][ni], a[mi], bf[ng][sel], bf[ng][sel + 2]);
                }
        }
        if (++s >= 3) s -= 3;
    }

    const int r0 = bm + wm + (lane >> 2);
    const int cb = bn + wn + 2 * (lane & 3);
    if (g.kSplit == 1) {
        if (g.outHalf) {
            __half* Cb = (__half*)g.C + (long)batch * g.bsC;
#pragma unroll
            for (int ni = 0; ni < 4; ni++) {
                int col = cb + ni * 8;
                float2 bv = {0.f, 0.f};
                if (g.bias) bv = *(const float2*)&g.bias[col];
#pragma unroll
                for (int mi = 0; mi < 2; mi++) {
                    int r = r0 + mi * 16;
                    if (r < g.Mreal)
                        *(__half2*)&Cb[(long)r * g.ldc + col] =
                            __floats2half2_rn(acc[mi][ni][0] + bv.x, acc[mi][ni][1] + bv.y);
                    if (r + 8 < g.Mreal)
                        *(__half2*)&Cb[(long)(r + 8) * g.ldc + col] =
                            __floats2half2_rn(acc[mi][ni][2] + bv.x, acc[mi][ni][3] + bv.y);
                }
            }
        } else {
            float* Cb = (float*)g.C + (long)batch * g.bsC;
#pragma unroll
            for (int ni = 0; ni < 4; ni++) {
                int col = cb + ni * 8;
                float2 bv = {0.f, 0.f};
                if (g.bias) bv = *(const float2*)&g.bias[col];
#pragma unroll
                for (int mi = 0; mi < 2; mi++) {
                    int r = r0 + mi * 16;
                    if (r < g.Mreal) {
                        float2 v0 = { acc[mi][ni][0] + bv.x, acc[mi][ni][1] + bv.y };
                        *(float2*)&Cb[(long)r * g.ldc + col] = v0;
                    }
                    if (r + 8 < g.Mreal) {
                        float2 v1 = { acc[mi][ni][2] + bv.x, acc[mi][ni][3] + bv.y };
                        *(float2*)&Cb[(long)(r + 8) * g.ldc + col] = v1;
                    }
                }
            }
        }
    } else {
        float* Cb = (float*)g.C + (long)batch * g.bsC;
#pragma unroll
        for (int ni = 0; ni < 4; ni++) {
            int col = cb + ni * 8;
#pragma unroll
            for (int mi = 0; mi < 2; mi++) {
                int r = r0 + mi * 16;
                if (r < g.Mreal) {
                    atomicAdd(&Cb[(long)r * g.ldc + col],     acc[mi][ni][0]);
                    atomicAdd(&Cb[(long)r * g.ldc + col + 1], acc[mi][ni][1]);
                }
                if (r + 8 < g.Mreal) {
                    atomicAdd(&Cb[(long)(r + 8) * g.ldc + col],     acc[mi][ni][2]);
                    atomicAdd(&Cb[(long)(r + 8) * g.ldc + col + 1], acc[mi][ni][3]);
                }
            }
        }
    }
}

// ---------------------------------------------------------------------------
// ctx_fused: per CTA (b, mtile, ntile): softmax 64 l-rows from g_sc into a
// resident smem A tile (fp16, zero-padded K to 224), then ctx GEMM vs keyT.
//   A: 64 x 232 halves (stride 464B, conflict-free ldmatrix); B streamed.
// ---------------------------------------------------------------------------
#define CTXA_STRIDE 232
#define CTXA_BYTES  (64 * CTXA_STRIDE * 2)    // 29696
#define CTX_STG     5120u
#define DSMEM_CTX   (CTXA_BYTES + 3 * 5120)   // 45056

__global__ __launch_bounds__(128) void ctx_fused(
    const float* __restrict__ gsc, const __half* __restrict__ gkeyT,
    __half* __restrict__ gctx)
{
    const int b   = blockIdx.x >> 4;
    const int rem = blockIdx.x & 15;
    const int bm  = (rem >> 3) * 64;
    const int bn  = (rem & 7) * 64;
    const int tid  = threadIdx.x;
    const int lane = tid & 31;
    const int wid  = tid >> 5;

    const uint32_t smem  = s2u(dynsm);
    const uint32_t smemB = smem + CTXA_BYTES;
    __half* asm_ = (__half*)dynsm;
    const __half* keyTb = gkeyT + (long)b * HD * KP;

    // B loader (keyT rows bn..bn+63, K tile of 32 halves)
    auto issue_tile = [&](int t, int s) {
        const int k0 = t << 5;
#pragma unroll
        for (int i = 0; i < 2; i++) {
            int idx = tid + (i << 7);
            int r = idx >> 2, c = idx & 3;
            uint32_t dst = smemB + s * CTX_STG + (uint32_t)(r * 80 + c * 16);
            cp16(dst, keyTb + (long)(bn + r) * KP + k0 + c * 8);
        }
    };

    // overlap: start B DMA before softmax
    issue_tile(0, 0); CP_COMMIT();
    issue_tile(1, 1); CP_COMMIT();

    // ---- phase A: softmax for rows bm..bm+63 (warp per row, 16 each) ----
    {
        const float sc1 = 1.0f / 32.0f;
        const float rs2 = 0.70710678118654752f;
        for (int it = 0; it < 16; it++) {
            int lrow = wid * 16 + it;
            const float* srow = gsc + (long)(b * LL + bm + lrow) * 256;
            __half* wrow = asm_ + lrow * CTXA_STRIDE;

            float vb[4], m = -1e30f;
#pragma unroll
            for (int ii = 0; ii < 4; ii++) {
                int jj = lane + 32 * ii;
                vb[ii] = (jj < SS) ? srow[jj] * sc1 : -1e30f;
                m = fmaxf(m, vb[ii]);
            }
#pragma unroll
            for (int off = 16; off; off >>= 1) m = fmaxf(m, __shfl_xor_sync(0xffffffffu, m, off));
            float sum = 0.f;
#pragma unroll
            for (int ii = 0; ii < 4; ii++) {
                int jj = lane + 32 * ii;
                if (jj < SS) { vb[ii] = __expf(vb[ii] - m); sum += vb[ii]; }
            }
#pragma unroll
            for (int off = 16; off; off >>= 1) sum += __shfl_xor_sync(0xffffffffu, sum, off);
            float inv = rs2 / sum;
#pragma unroll
            for (int ii = 0; ii < 4; ii++) {
                int jj = lane + 32 * ii;
                if (jj < SS) wrow[jj] = __float2half_rn(vb[ii] * inv);
            }

            m = -1e30f;
#pragma unroll
            for (int ii = 0; ii < 4; ii++) {
                int jj = lane + 32 * ii;
                vb[ii] = (jj < TT) ? -srow[SS + jj] * sc1 : -1e30f;
                m = fmaxf(m, vb[ii]);
            }
#pragma unroll
            for (int off = 16; off; off >>= 1) m = fmaxf(m, __shfl_xor_sync(0xffffffffu, m, off));
            sum = 0.f;
#pragma unroll
            for (int ii = 0; ii < 4; ii++) {
                int jj = lane + 32 * ii;
                if (jj < TT) { vb[ii] = __expf(vb[ii] - m); sum += vb[ii]; }
            }
#pragma unroll
            for (int off = 16; off; off >>= 1) sum += __shfl_xor_sync(0xffffffffu, sum, off);
            inv = -rs2 / sum;
#pragma unroll
            for (int ii = 0; ii < 4; ii++) {
                int jj = lane + 32 * ii;
                if (jj < TT)                      wrow[SS + jj] = __float2half_rn(vb[ii] * inv);
                else if (SS + jj < CTXA_STRIDE)   wrow[SS + jj] = __half(0.f);  // zero pads
            }
        }
    }
    __syncthreads();

    // ---- phase B: GEMM, A resident in smem, B streamed (T = 7) ----
    const int lr     = lane & 7;
    const int rowoff = ((lane >> 3) & 1) * 8;
    const int coff   = lane >> 4;
    const int wm     = (wid & 1) * 32;
    const int wn     = (wid >> 1) * 32;
    const int arow   = wm + rowoff + lr;
    const int brow   = wn + rowoff + lr;

    float acc[2][4][4];
#pragma unroll
    for (int mi = 0; mi < 2; mi++)
#pragma unroll
        for (int ni = 0; ni < 4; ni++)
#pragma unroll
            for (int j = 0; j < 4; j++) acc[mi][ni][j] = 0.f;

    int s = 0;
    for (int t = 0; t < 7; t++) {
        CP_WAITG(1);
        __syncthreads();
        int sn = s + 2; if (sn >= 3) sn -= 3;
        if (t + 2 < 7) issue_tile(t + 2, sn);
        CP_COMMIT();

        const uint32_t bb = smemB + s * CTX_STG;
#pragma unroll
        for (int ks = 0; ks < 2; ks++) {
            uint32_t a[2][4], bf[2][4];
#pragma unroll
            for (int mi = 0; mi < 2; mi++) {
                uint32_t ad = smem + (uint32_t)((arow + mi * 16) * 464 + t * 64 + ks * 32 + coff * 16);
                LDSM4(a[mi], ad);
            }
#pragma unroll
            for (int ng = 0; ng < 2; ng++) {
                uint32_t bd = bb + (uint32_t)((brow + ng * 16) * 80 + ((ks << 1) + coff) * 16);
                LDSM4(bf[ng], bd);
            }
#pragma unroll
            for (int mi = 0; mi < 2; mi++)
#pragma unroll
                for (int ni = 0; ni < 4; ni++) {
                    int ng = ni >> 1, sel = ni & 1;
                    MMA_F16(acc[mi][ni], a[mi], bf[ng][sel], bf[ng][sel + 2]);
                }
        }
        if (++s >= 3) s -= 3;
    }

    // epilogue: fp16 store
    __half* Cb = gctx + (long)b * LL * HD;
    const int r0 = bm + wm + (lane >> 2);
    const int cb = bn + wn + 2 * (lane & 3);
#pragma unroll
    for (int ni = 0; ni < 4; ni++) {
        int col = cb + ni * 8;
#pragma unroll
        for (int mi = 0; mi < 2; mi++) {
            int r = r0 + mi * 16;
            *(__half2*)&Cb[(long)r * HD + col] =
                __floats2half2_rn(acc[mi][ni][0], acc[mi][ni][1]);
            *(__half2*)&Cb[(long)(r + 8) * HD + col] =
                __floats2half2_rn(acc[mi][ni][2], acc[mi][ni][3]);
        }
    }
}

// ---------------------------------------------------------------------------
extern "C" void kernel_launch(void* const* d_in, const int* in_sizes, int n_in,
                              void* d_out, int out_size)
{
    const float* query = (const float*)d_in[0];
    const float* src   = (const float*)d_in[1];
    const float* trg   = (const float*)d_in[2];
    const float* Wq    = (const float*)d_in[3];
    const float* bq    = (const float*)d_in[4];
    const float* Ws    = (const float*)d_in[5];
    const float* bs    = (const float*)d_in[6];
    const float* Wo    = (const float*)d_in[7];
    const float* bo    = (const float*)d_in[8];
    float* out = (float*)d_out;

    __half *q16, *s16, *t16, *qbuf, *keybuf, *keyTbuf, *ctxbuf, *wqT, *wsT, *woT;
    float *scbuf;
    cudaGetSymbolAddress((void**)&q16,     g_in_q);
    cudaGetSymbolAddress((void**)&s16,     g_in_s);
    cudaGetSymbolAddress((void**)&t16,     g_in_t);
    cudaGetSymbolAddress((void**)&qbuf,    g_q);
    cudaGetSymbolAddress((void**)&keybuf,  g_key);
    cudaGetSymbolAddress((void**)&keyTbuf, g_keyT);
    cudaGetSymbolAddress((void**)&ctxbuf,  g_ctx);
    cudaGetSymbolAddress((void**)&scbuf,   g_sc);
    cudaGetSymbolAddress((void**)&wqT,     g_wqT);
    cudaGetSymbolAddress((void**)&wsT,     g_wsT);
    cudaGetSymbolAddress((void**)&woT,     g_woT);

    cudaFuncSetAttribute(ctx_fused, cudaFuncAttributeMaxDynamicSharedMemorySize, DSMEM_CTX);

    AUXT auxNone = { 0, 0, 0 };

    // Launch 1: prep (transposes + input conversion)
    prepAll<<<1792 + 1856, 256>>>(Wq, wqT, Ws, wsT, Wo, woT,
                                  query, src, trg, q16, s16, t16);

    // Launch 2: key-proj + q-proj + out1 (all kSplit=1, bias fused)
    GD dKey = { s16, t16, BB * SS, FD, 0,   wsT, wsT, 1 << 30, FD, 0,
                keybuf, 512, 0,  bs,  FD, 1, 1,  BB * (SS + TT), 512,  25, 8, 1 };
    GD dQ   = { q16, q16, 1 << 30, QD, 0,   wqT, wqT, 1 << 30, QD, 0,
                qbuf, 512, 0,  bq,  QD, 1, 1,  BB * LL, 512,  16, 8, 1 };
    GD dO1  = { q16, q16, 1 << 30, QD, 0,   woT, woT, 1 << 30, QD + HD, 0,
                out, 512, 0,  bo,  QD, 1, 0,  BB * LL, 512,  16, 8, 1 };
    gemm_mma<<<456, 128, DSMEM_G>>>(dKey, dQ, dO1, 200, 328, auxNone);

    // Launch 3: scores GEMM (64 CTAs, ks1 direct store) + keyT transpose (256)
    GD dSc = { qbuf, qbuf, 1 << 30, HD, LL * HD,
               keybuf, keybuf + (long)BB * SS * HD, SS, HD, SS * HD,
               scbuf, 256, LL * 256,  (const float*)0,  HD, 1, 0,
               LL, SS + TT,  2, 4, BB };
    AUXT aux3 = { keybuf, keyTbuf, 64 };
    gemm_mma<<<64 + 256, 128, DSMEM_G>>>(dSc, dSc, dSc, 64, 64, aux3);

    // Launch 4: fused softmax + ctx GEMM (128 CTAs)
    ctx_fused<<<128, 128, DSMEM_CTX>>>(scbuf, keyTbuf, ctxbuf);

    // Launch 5: out2 = ctx @ Wo[512:], split-K x2, atomic into out
    GD dO2 = { ctxbuf, ctxbuf, 1 << 30, HD, 0,
               woT + QD, woT + QD, 1 << 30, QD + HD, 0,
               out, 512, 0,  (const float*)0,  HD, 2, 0,  BB * LL, 512,  16, 8, 1 };
    gemm_mma<<<256, 128, DSMEM_G>>>(dO2, dO2, dO2, 256, 256, auxNone);
}